// round 7
// baseline (speedup 1.0000x reference)
#include <cuda_runtime.h>
#include <cuda_fp16.h>
#include <math.h>
#include <stdint.h>

#define CC 256
#define NN 4096
#define BB 16
#define NH 8
#define HD 32
#define HH 64
#define WW 64
#define M_QKV 768
#define SEGS 8

// ---------------- scratch (device globals; no allocation allowed) ----------------
__device__ float g_qkv[(size_t)BB * M_QKV * NN];   // (B, 768, N) fp32: q | k | v
__device__ float g_kvp[SEGS * BB * NH * HD * HD];  // partial kv states
__device__ float g_ksp[SEGS * BB * NH * HD];       // partial ksums
__device__ float g_bcat[M_QKV];
__device__ float g_invscale[CC];
// fp16 buffers (uint4-typed for 16B alignment)
__device__ uint4 g_wh4 [M_QKV * CC * 2 / 16];              // W fp16
__device__ uint4 g_pwh4[CC * CC * 2 / 16];                 // Wproj fp16
__device__ uint4 g_xh4 [(size_t)BB * CC * NN * 2 / 16];    // x fp16
__device__ uint4 g_mh4 [(size_t)BB * CC * NN * 2 / 16];    // mid fp16

// ---------------- ptx helpers (baseline sm_80+ ISA only) ----------------
__device__ __forceinline__ uint32_t smem_u32(const void* p) {
    uint32_t a;
    asm("{ .reg .u64 t; cvta.to.shared.u64 t, %1; cvt.u32.u64 %0, t; }" : "=r"(a) : "l"(p));
    return a;
}
__device__ __forceinline__ void cp_async16(uint32_t saddr, const void* gptr) {
    asm volatile("cp.async.cg.shared.global [%0], [%1], 16;"
                 :: "r"(saddr), "l"(__cvta_generic_to_global(gptr)) : "memory");
}
__device__ __forceinline__ void ldsm_x4(uint32_t* r, uint32_t addr) {
    asm volatile("ldmatrix.sync.aligned.m8n8.x4.shared.b16 {%0,%1,%2,%3}, [%4];"
                 : "=r"(r[0]), "=r"(r[1]), "=r"(r[2]), "=r"(r[3]) : "r"(addr));
}
__device__ __forceinline__ void ldsm_x4_t(uint32_t* r, uint32_t addr) {
    asm volatile("ldmatrix.sync.aligned.m8n8.x4.trans.shared.b16 {%0,%1,%2,%3}, [%4];"
                 : "=r"(r[0]), "=r"(r[1]), "=r"(r[2]), "=r"(r[3]) : "r"(addr));
}
__device__ __forceinline__ void mma_f16(float* c, const uint32_t* a, uint32_t b0, uint32_t b1) {
    asm volatile(
        "mma.sync.aligned.m16n8k16.row.col.f32.f16.f16.f32 "
        "{%0,%1,%2,%3}, {%4,%5,%6,%7}, {%8,%9}, {%0,%1,%2,%3};"
        : "+f"(c[0]), "+f"(c[1]), "+f"(c[2]), "+f"(c[3])
        : "r"(a[0]), "r"(a[1]), "r"(a[2]), "r"(a[3]), "r"(b0), "r"(b1));
}

// ---------------- prep: weight fp16 + biases + inv softplus scale ----------------
__global__ void prep_kernel(const float* __restrict__ Wq, const float* __restrict__ bq,
                            const float* __restrict__ Wkv, const float* __restrict__ bkv,
                            const float* __restrict__ Wproj, const float* __restrict__ scale_param) {
    int r = blockIdx.x, t = threadIdx.x;
    float w = (r < CC) ? Wq[(size_t)r * CC + t] : Wkv[(size_t)(r - CC) * CC + t];
    ((__half*)g_wh4)[(size_t)r * CC + t] = __float2half(w);
    if (r < CC)
        ((__half*)g_pwh4)[r * CC + t] = __float2half(Wproj[(size_t)r * CC + t]);
    if (t == 0) {
        g_bcat[r] = (r < CC) ? bq[r] : bkv[r - CC];
        if (r < CC) {
            float s = scale_param[r];
            float sp = (s > 20.f) ? s : log1pf(expf(s));
            g_invscale[r] = 1.0f / sp;
        }
    }
}

// ---------------- convert fp32 -> fp16 ----------------
__global__ __launch_bounds__(256)
void split_kernel(const float4* __restrict__ src, __half* __restrict__ dst, int n4) {
    int i = blockIdx.x * 256 + threadIdx.x;
    if (i >= n4) return;
    float4 v = src[i];
    __half2* dp = (__half2*)(dst + 4 * (size_t)i);
    dp[0] = __halves2half2(__float2half(v.x), __float2half(v.y));
    dp[1] = __halves2half2(__float2half(v.z), __float2half(v.w));
}

// ---------------- mma.sync fp16 GEMM: out[b] = A(Mx256) @ B[b](256x4096) + bias ----------------
// Single-term fp16 (rel err ~3e-4). CTA 128x128, 8 warps of 32x64, 4-stage cp.async ring,
// 2 CTAs/SM.
#define STAGES 4
#define NCHUNK 8
#define A_STRIDE 80
#define B_STRIDE 272
#define A_TILE 10240
#define B_TILE 8704
#define STAGE_BYTES (A_TILE + B_TILE)      // 18944
#define SM_GEMM (STAGES * STAGE_BYTES)     // 75776

__global__ __launch_bounds__(256, 2)
void gemm_mma_kernel(const __half* __restrict__ A, const __half* __restrict__ B,
                     const float* __restrict__ bias, float* __restrict__ out, int M) {
    extern __shared__ char smem[];
    uint32_t sb = smem_u32(smem);
    int tid = threadIdx.x, lane = tid & 31, wid = tid >> 5;
    int n0 = blockIdx.x * 128;
    int mbase = blockIdx.y * 128;
    int bz = blockIdx.z;
    int wm = (wid & 3) * 32;
    int wn = (wid >> 2) * 64;

    const __half* Am = A + (size_t)mbase * CC;
    const __half* Bb = B + (size_t)bz * CC * NN;

    float acc[2][8][4];
#pragma unroll
    for (int mt = 0; mt < 2; mt++)
#pragma unroll
        for (int nt = 0; nt < 8; nt++)
#pragma unroll
            for (int i = 0; i < 4; i++) acc[mt][nt][i] = 0.f;

    int a_row0 = (tid * 2) >> 2, a_kc0 = (tid * 2) & 3;
    int a_row1 = (tid * 2 + 1) >> 2, a_kc1 = (tid * 2 + 1) & 3;
    int b_row0 = (tid * 2) >> 4, b_nc0 = (tid * 2) & 15;
    int b_row1 = (tid * 2 + 1) >> 4, b_nc1 = (tid * 2 + 1) & 15;

    auto issue_load = [&](int ck) {
        if (ck < NCHUNK) {
            int kb = ck * 32;
            uint32_t st = sb + (uint32_t)(ck & (STAGES - 1)) * STAGE_BYTES;
            cp_async16(st + a_row0 * A_STRIDE + a_kc0 * 16,
                       Am + (size_t)a_row0 * CC + kb + a_kc0 * 8);
            cp_async16(st + a_row1 * A_STRIDE + a_kc1 * 16,
                       Am + (size_t)a_row1 * CC + kb + a_kc1 * 8);
            cp_async16(st + A_TILE + b_row0 * B_STRIDE + b_nc0 * 16,
                       Bb + (size_t)(kb + b_row0) * NN + n0 + b_nc0 * 8);
            cp_async16(st + A_TILE + b_row1 * B_STRIDE + b_nc1 * 16,
                       Bb + (size_t)(kb + b_row1) * NN + n0 + b_nc1 * 8);
        }
        asm volatile("cp.async.commit_group;" ::: "memory");
    };

    issue_load(0);
    issue_load(1);
    issue_load(2);

    int li = lane >> 3, lr = lane & 7;

    for (int ck = 0; ck < NCHUNK; ck++) {
        asm volatile("cp.async.wait_group 2;" ::: "memory");
        __syncthreads();
        issue_load(ck + 3);

        uint32_t st = sb + (uint32_t)(ck & (STAGES - 1)) * STAGE_BYTES;
#pragma unroll
        for (int ks = 0; ks < 2; ks++) {
            uint32_t af[2][4];
#pragma unroll
            for (int mt = 0; mt < 2; mt++) {
                uint32_t addr = st + (uint32_t)(wm + mt * 16 + (li & 1) * 8 + lr) * A_STRIDE
                                   + (uint32_t)(ks * 32 + (li >> 1) * 16);
                ldsm_x4(af[mt], addr);
            }
#pragma unroll
            for (int j = 0; j < 4; j++) {
                uint32_t addr = st + A_TILE
                              + (uint32_t)(ks * 16 + (li & 1) * 8 + lr) * B_STRIDE
                              + (uint32_t)(wn + j * 16 + (li >> 1) * 8) * 2;
                uint32_t t4[4];
                ldsm_x4_t(t4, addr);
#pragma unroll
                for (int mt = 0; mt < 2; mt++) {
                    mma_f16(acc[mt][2 * j],     af[mt], t4[0], t4[1]);
                    mma_f16(acc[mt][2 * j + 1], af[mt], t4[2], t4[3]);
                }
            }
        }
        __syncthreads();
    }

    int g = lane >> 2, tg = lane & 3;
#pragma unroll
    for (int mt = 0; mt < 2; mt++) {
        int m = mbase + wm + mt * 16 + g;
        float bv0 = bias[m], bv1 = bias[m + 8];
        float* po0 = out + ((size_t)bz * M + m) * NN + n0 + wn + tg * 2;
        float* po1 = po0 + 8 * (size_t)NN;
#pragma unroll
        for (int nt = 0; nt < 8; nt++) {
            *(float2*)(po0 + nt * 8) = make_float2(acc[mt][nt][0] + bv0, acc[mt][nt][1] + bv0);
            *(float2*)(po1 + nt * 8) = make_float2(acc[mt][nt][2] + bv1, acc[mt][nt][3] + bv1);
        }
    }
}

// ---------------- single-pass focusing transform (q and k), 32 pixels/block ----------------
#define FOC_PIX 32
#define FOC_STR 33
#define FOC_SMEM (256 * FOC_STR * 4 + 256 * 4 + 256 * 4 + 256 * 4 + FOC_PIX * 4)
__global__ __launch_bounds__(256)
void focus_kernel() {
    extern __shared__ char fsm[];
    float* tile = (float*)fsm;                            // 256 x 33
    float* sinv = (float*)(fsm + 256 * FOC_STR * 4);      // 256
    float* sp2  = sinv + 256;                             // 8 x 32
    float* sp6  = sp2 + 256;                              // 8 x 32
    float* sf   = sp6 + 256;                              // 32
    int tid = threadIdx.x;
    int part = blockIdx.y, b = blockIdx.z;
    int n0 = blockIdx.x * FOC_PIX;
    sinv[tid] = g_invscale[tid];
    float* base = g_qkv + ((size_t)b * M_QKV + part * CC) * NN + n0;
    int j = tid & 31, ci = tid >> 5;
    __syncthreads();
#pragma unroll 8
    for (int i = 0; i < 32; i++) {
        int c = i * 8 + ci;
        float v = base[(size_t)c * NN + j];
        v = fmaxf(v, 0.f) + 1e-6f;
        tile[c * FOC_STR + j] = v * sinv[c];
    }
    __syncthreads();
    float s2 = 0.f, s6 = 0.f;
#pragma unroll 8
    for (int c = ci * 32; c < ci * 32 + 32; c++) {
        float v = tile[c * FOC_STR + j];
        float v2 = v * v, v3 = v2 * v;
        s2 += v2; s6 += v3 * v3;
        tile[c * FOC_STR + j] = v3;
    }
    sp2[ci * 32 + j] = s2;
    sp6[ci * 32 + j] = s6;
    __syncthreads();
    if (tid < 32) {
        float t2 = 0.f, t6 = 0.f;
#pragma unroll
        for (int gq = 0; gq < 8; gq++) { t2 += sp2[gq * 32 + tid]; t6 += sp6[gq * 32 + tid]; }
        sf[tid] = sqrtf(t2 / t6);
    }
    __syncthreads();
    float f = sf[j];
#pragma unroll 8
    for (int i = 0; i < 32; i++) {
        int c = i * 8 + ci;
        base[(size_t)c * NN + j] = tile[c * FOC_STR + j] * f;
    }
}

// ---------------- per-head kv_state partials: j-major smem, float4 inner loads ----------------
#define CHUNK 128
#define JSTR 36
__global__ __launch_bounds__(256)
void kvstate_kernel() {
    int bh = blockIdx.x, seg = blockIdx.y;
    int b = bh >> 3, h = bh & 7;
    const float* kbase = g_qkv + ((size_t)b * M_QKV + CC + h * HD) * NN;
    const float* vbase = g_qkv + ((size_t)b * M_QKV + 2 * CC + h * HD) * NN;
    __shared__ __align__(16) float sk[CHUNK * JSTR];
    __shared__ __align__(16) float sv[CHUNK * JSTR];
    int tid = threadIdx.x;
    int c = tid >> 3, d4 = (tid & 7) * 4;
    int lc = tid >> 3, lj4 = (tid & 7) * 4;
    float acc[4] = {0, 0, 0, 0};
    float ks = 0.f;
    int j_begin = seg * (NN / SEGS);

    for (int j0 = j_begin; j0 < j_begin + NN / SEGS; j0 += CHUNK) {
#pragma unroll
        for (int jj = 0; jj < CHUNK; jj += 32) {
            float4 k4 = *(const float4*)(kbase + (size_t)lc * NN + j0 + jj + lj4);
            float4 v4 = *(const float4*)(vbase + (size_t)lc * NN + j0 + jj + lj4);
            sk[(jj + lj4 + 0) * JSTR + lc] = k4.x;
            sk[(jj + lj4 + 1) * JSTR + lc] = k4.y;
            sk[(jj + lj4 + 2) * JSTR + lc] = k4.z;
            sk[(jj + lj4 + 3) * JSTR + lc] = k4.w;
            sv[(jj + lj4 + 0) * JSTR + lc] = v4.x;
            sv[(jj + lj4 + 1) * JSTR + lc] = v4.y;
            sv[(jj + lj4 + 2) * JSTR + lc] = v4.z;
            sv[(jj + lj4 + 3) * JSTR + lc] = v4.w;
        }
        __syncthreads();
#pragma unroll 4
        for (int j = 0; j < CHUNK; j++) {
            float kc = sk[j * JSTR + c];
            ks += kc;
            float4 v = *(const float4*)(sv + j * JSTR + d4);
            acc[0] += kc * v.x;
            acc[1] += kc * v.y;
            acc[2] += kc * v.z;
            acc[3] += kc * v.w;
        }
        __syncthreads();
    }
    float* kvs = g_kvp + ((size_t)seg * BB * NH + bh) * HD * HD;
#pragma unroll
    for (int i = 0; i < 4; i++) kvs[c * HD + d4 + i] = acc[i];
    if ((tid & 7) == 0) g_ksp[((size_t)seg * BB * NH + bh) * HD + c] = ks;
}

// ---------------- fused depthwise conv + attention output -> fp16 mid ----------------
__global__ __launch_bounds__(256)
void conv_attn_kernel(const float* __restrict__ dwc_w, const float* __restrict__ dwc_b) {
    __shared__ float skvs[HD * HD];
    __shared__ float sks[HD];
    __shared__ float tile4[4][20][21];
    __shared__ float wloc4[4][25];
    int bh = blockIdx.y;
    int b = bh >> 3, h = bh & 7;
    int ty0 = (blockIdx.x >> 2) * 16;
    int tx0 = (blockIdx.x & 3) * 16;
    int tid = threadIdx.x, lx = tid & 15, ly = tid >> 4;
    int gy = ty0 + ly, gx = tx0 + lx;
    int n = gy * WW + gx;

    for (int i = tid; i < HD * HD; i += 256) {
        float s = 0.f;
#pragma unroll
        for (int seg = 0; seg < SEGS; seg++)
            s += g_kvp[((size_t)seg * BB * NH + bh) * HD * HD + i];
        skvs[i] = s;
    }
    if (tid < HD) {
        float s = 0.f;
#pragma unroll
        for (int seg = 0; seg < SEGS; seg++)
            s += g_ksp[((size_t)seg * BB * NH + bh) * HD + tid];
        sks[tid] = s;
    }

    float acc[HD];
    const float* vball = g_qkv + ((size_t)b * M_QKV + 2 * CC + h * HD) * NN;
    for (int d0 = 0; d0 < HD; d0 += 4) {
        __syncthreads();
        if (tid < 100) wloc4[tid / 25][tid % 25] = dwc_w[(d0 + tid / 25) * 25 + tid % 25];
        for (int i = tid; i < 1600; i += 256) {
            int ch = i / 400, r = i % 400;
            int ry = r / 20, rx = r % 20;
            int sy = ty0 - 2 + ry, sx = tx0 - 2 + rx;
            float v = 0.f;
            if (sy >= 0 && sy < HH && sx >= 0 && sx < WW)
                v = vball[(size_t)(d0 + ch) * NN + sy * WW + sx];
            tile4[ch][ry][rx] = v;
        }
        __syncthreads();
#pragma unroll
        for (int ch = 0; ch < 4; ch++) {
            float a = dwc_b[d0 + ch];
#pragma unroll
            for (int ky = 0; ky < 5; ky++)
#pragma unroll
                for (int kx = 0; kx < 5; kx++)
                    a += tile4[ch][ly + ky][lx + kx] * wloc4[ch][ky * 5 + kx];
            acc[d0 + ch] = a;
        }
    }
    __syncthreads();

    const float* qbase = g_qkv + ((size_t)b * M_QKV + h * HD) * NN + n;
    float a2[HD];
#pragma unroll
    for (int d = 0; d < HD; d++) a2[d] = 0.f;
    float zacc = 0.f;
#pragma unroll
    for (int c = 0; c < HD; c++) {
        float qv = qbase[(size_t)c * NN];
        zacc += qv * sks[c];
#pragma unroll
        for (int d = 0; d < HD; d++) a2[d] += qv * skvs[c * HD + d];
    }
    float z = 1.0f / (zacc + 1e-6f);
    __half* mh = (__half*)g_mh4;
#pragma unroll
    for (int d = 0; d < HD; d++) {
        size_t off = ((size_t)b * CC + h * HD + d) * NN + n;
        mh[off] = __float2half(acc[d] + a2[d] * z);
    }
}

// ---------------- launch ----------------
extern "C" void kernel_launch(void* const* d_in, const int* in_sizes, int n_in,
                              void* d_out, int out_size) {
    const float* x           = (const float*)d_in[0];
    const float* Wq          = (const float*)d_in[1];
    const float* bq          = (const float*)d_in[2];
    const float* Wkv         = (const float*)d_in[3];
    const float* bkv         = (const float*)d_in[4];
    const float* Wproj       = (const float*)d_in[5];
    const float* bproj       = (const float*)d_in[6];
    const float* dwc_w       = (const float*)d_in[7];
    const float* dwc_b       = (const float*)d_in[8];
    const float* scale_param = (const float*)d_in[9];
    float* out = (float*)d_out;

    float *p_qkv, *p_bcat;
    uint4 *p_wh, *p_pwh, *p_xh, *p_mh;
    cudaGetSymbolAddress((void**)&p_qkv,  g_qkv);
    cudaGetSymbolAddress((void**)&p_bcat, g_bcat);
    cudaGetSymbolAddress((void**)&p_wh,   g_wh4);
    cudaGetSymbolAddress((void**)&p_pwh,  g_pwh4);
    cudaGetSymbolAddress((void**)&p_xh,   g_xh4);
    cudaGetSymbolAddress((void**)&p_mh,   g_mh4);

    cudaFuncSetAttribute(gemm_mma_kernel, cudaFuncAttributeMaxDynamicSharedMemorySize, SM_GEMM);
    cudaFuncSetAttribute(focus_kernel, cudaFuncAttributeMaxDynamicSharedMemorySize, FOC_SMEM);

    prep_kernel<<<M_QKV, CC>>>(Wq, bq, Wkv, bkv, Wproj, scale_param);

    int n4 = BB * CC * NN / 4;
    split_kernel<<<(n4 + 255) / 256, 256>>>((const float4*)x, (__half*)p_xh, n4);

    // QKV projection: 768x256 @ 256x4096 per batch
    gemm_mma_kernel<<<dim3(NN / 128, M_QKV / 128, BB), 256, SM_GEMM>>>(
        (const __half*)p_wh, (const __half*)p_xh, p_bcat, p_qkv, M_QKV);

    focus_kernel<<<dim3(NN / FOC_PIX, 2, BB), 256, FOC_SMEM>>>();

    kvstate_kernel<<<dim3(BB * NH, SEGS), 256>>>();

    conv_attn_kernel<<<dim3(16, BB * NH), 256>>>(dwc_w, dwc_b);

    // Output projection: 256x256 @ 256x4096 per batch -> d_out
    gemm_mma_kernel<<<dim3(NN / 128, CC / 128, BB), 256, SM_GEMM>>>(
        (const __half*)p_pwh, (const __half*)p_mh, bproj, out, CC);
}

// round 8
// speedup vs baseline: 1.4532x; 1.4532x over previous
#include <cuda_runtime.h>
#include <cuda_fp16.h>
#include <math.h>
#include <stdint.h>

#define CC 256
#define NN 4096
#define BB 16
#define NH 8
#define HD 32
#define HH 64
#define WW 64
#define M_QKV 768
#define SEGS 8

// ---------------- scratch (device globals; no allocation allowed) ----------------
__device__ float g_qkv[(size_t)BB * M_QKV * NN];   // (B, 768, N) fp32: q | k | v
__device__ float g_kvp[SEGS * BB * NH * HD * HD];  // partial kv states
__device__ float g_ksp[SEGS * BB * NH * HD];       // partial ksums
__device__ float g_bcat[M_QKV];
__device__ float g_invscale[CC];
// fp16 buffers (uint4-typed for 16B alignment)
__device__ uint4 g_wh4 [M_QKV * CC * 2 / 16];              // W fp16
__device__ uint4 g_pwh4[CC * CC * 2 / 16];                 // Wproj fp16
__device__ uint4 g_xh4 [(size_t)BB * CC * NN * 2 / 16];    // x fp16
__device__ uint4 g_mh4 [(size_t)BB * CC * NN * 2 / 16];    // mid fp16

// ---------------- ptx helpers (baseline sm_80+ ISA only) ----------------
__device__ __forceinline__ uint32_t smem_u32(const void* p) {
    uint32_t a;
    asm("{ .reg .u64 t; cvta.to.shared.u64 t, %1; cvt.u32.u64 %0, t; }" : "=r"(a) : "l"(p));
    return a;
}
__device__ __forceinline__ void cp_async16(uint32_t saddr, const void* gptr) {
    asm volatile("cp.async.cg.shared.global [%0], [%1], 16;"
                 :: "r"(saddr), "l"(__cvta_generic_to_global(gptr)) : "memory");
}
__device__ __forceinline__ void ldsm_x4(uint32_t* r, uint32_t addr) {
    asm volatile("ldmatrix.sync.aligned.m8n8.x4.shared.b16 {%0,%1,%2,%3}, [%4];"
                 : "=r"(r[0]), "=r"(r[1]), "=r"(r[2]), "=r"(r[3]) : "r"(addr));
}
__device__ __forceinline__ void ldsm_x4_t(uint32_t* r, uint32_t addr) {
    asm volatile("ldmatrix.sync.aligned.m8n8.x4.trans.shared.b16 {%0,%1,%2,%3}, [%4];"
                 : "=r"(r[0]), "=r"(r[1]), "=r"(r[2]), "=r"(r[3]) : "r"(addr));
}
__device__ __forceinline__ void mma_f16(float* c, const uint32_t* a, uint32_t b0, uint32_t b1) {
    asm volatile(
        "mma.sync.aligned.m16n8k16.row.col.f32.f16.f16.f32 "
        "{%0,%1,%2,%3}, {%4,%5,%6,%7}, {%8,%9}, {%0,%1,%2,%3};"
        : "+f"(c[0]), "+f"(c[1]), "+f"(c[2]), "+f"(c[3])
        : "r"(a[0]), "r"(a[1]), "r"(a[2]), "r"(a[3]), "r"(b0), "r"(b1));
}

// ---------------- prep: weight fp16 + biases + inv softplus scale ----------------
__global__ void prep_kernel(const float* __restrict__ Wq, const float* __restrict__ bq,
                            const float* __restrict__ Wkv, const float* __restrict__ bkv,
                            const float* __restrict__ Wproj, const float* __restrict__ scale_param) {
    int r = blockIdx.x, t = threadIdx.x;
    float w = (r < CC) ? Wq[(size_t)r * CC + t] : Wkv[(size_t)(r - CC) * CC + t];
    ((__half*)g_wh4)[(size_t)r * CC + t] = __float2half(w);
    if (r < CC)
        ((__half*)g_pwh4)[r * CC + t] = __float2half(Wproj[(size_t)r * CC + t]);
    if (t == 0) {
        g_bcat[r] = (r < CC) ? bq[r] : bkv[r - CC];
        if (r < CC) {
            float s = scale_param[r];
            float sp = (s > 20.f) ? s : log1pf(expf(s));
            g_invscale[r] = 1.0f / sp;
        }
    }
}

// ---------------- convert fp32 -> fp16 ----------------
__global__ __launch_bounds__(256)
void split_kernel(const float4* __restrict__ src, __half* __restrict__ dst, int n4) {
    int i = blockIdx.x * 256 + threadIdx.x;
    if (i >= n4) return;
    float4 v = src[i];
    __half2* dp = (__half2*)(dst + 4 * (size_t)i);
    dp[0] = __halves2half2(__float2half(v.x), __float2half(v.y));
    dp[1] = __halves2half2(__float2half(v.z), __float2half(v.w));
}

// ---------------- mma.sync fp16 GEMM: out[b] = A(Mx256) @ B[b](256x4096) + bias ----------------
// Single-term fp16 (rel err ~2.4e-4). CTA 128x128, 8 warps of 32x64, 4-stage cp.async ring.
// NO min-blocks launch bound: let the compiler keep all 64 accumulators in registers.
#define STAGES 4
#define NCHUNK 8
#define A_STRIDE 80
#define B_STRIDE 272
#define A_TILE 10240
#define B_TILE 8704
#define STAGE_BYTES (A_TILE + B_TILE)      // 18944
#define SM_GEMM (STAGES * STAGE_BYTES)     // 75776

__global__ __launch_bounds__(256)
void gemm_mma_kernel(const __half* __restrict__ A, const __half* __restrict__ B,
                     const float* __restrict__ bias, float* __restrict__ out, int M) {
    extern __shared__ char smem[];
    uint32_t sb = smem_u32(smem);
    int tid = threadIdx.x, lane = tid & 31, wid = tid >> 5;
    int n0 = blockIdx.x * 128;
    int mbase = blockIdx.y * 128;
    int bz = blockIdx.z;
    int wm = (wid & 3) * 32;
    int wn = (wid >> 2) * 64;

    const __half* Am = A + (size_t)mbase * CC;
    const __half* Bb = B + (size_t)bz * CC * NN;

    float acc[2][8][4];
#pragma unroll
    for (int mt = 0; mt < 2; mt++)
#pragma unroll
        for (int nt = 0; nt < 8; nt++)
#pragma unroll
            for (int i = 0; i < 4; i++) acc[mt][nt][i] = 0.f;

    int a_row0 = (tid * 2) >> 2, a_kc0 = (tid * 2) & 3;
    int a_row1 = (tid * 2 + 1) >> 2, a_kc1 = (tid * 2 + 1) & 3;
    int b_row0 = (tid * 2) >> 4, b_nc0 = (tid * 2) & 15;
    int b_row1 = (tid * 2 + 1) >> 4, b_nc1 = (tid * 2 + 1) & 15;

    auto issue_load = [&](int ck) {
        if (ck < NCHUNK) {
            int kb = ck * 32;
            uint32_t st = sb + (uint32_t)(ck & (STAGES - 1)) * STAGE_BYTES;
            cp_async16(st + a_row0 * A_STRIDE + a_kc0 * 16,
                       Am + (size_t)a_row0 * CC + kb + a_kc0 * 8);
            cp_async16(st + a_row1 * A_STRIDE + a_kc1 * 16,
                       Am + (size_t)a_row1 * CC + kb + a_kc1 * 8);
            cp_async16(st + A_TILE + b_row0 * B_STRIDE + b_nc0 * 16,
                       Bb + (size_t)(kb + b_row0) * NN + n0 + b_nc0 * 8);
            cp_async16(st + A_TILE + b_row1 * B_STRIDE + b_nc1 * 16,
                       Bb + (size_t)(kb + b_row1) * NN + n0 + b_nc1 * 8);
        }
        asm volatile("cp.async.commit_group;" ::: "memory");
    };

    issue_load(0);
    issue_load(1);
    issue_load(2);

    int li = lane >> 3, lr = lane & 7;

    for (int ck = 0; ck < NCHUNK; ck++) {
        asm volatile("cp.async.wait_group 2;" ::: "memory");
        __syncthreads();
        issue_load(ck + 3);

        uint32_t st = sb + (uint32_t)(ck & (STAGES - 1)) * STAGE_BYTES;
#pragma unroll
        for (int ks = 0; ks < 2; ks++) {
            uint32_t af[2][4];
#pragma unroll
            for (int mt = 0; mt < 2; mt++) {
                uint32_t addr = st + (uint32_t)(wm + mt * 16 + (li & 1) * 8 + lr) * A_STRIDE
                                   + (uint32_t)(ks * 32 + (li >> 1) * 16);
                ldsm_x4(af[mt], addr);
            }
#pragma unroll
            for (int j = 0; j < 4; j++) {
                uint32_t addr = st + A_TILE
                              + (uint32_t)(ks * 16 + (li & 1) * 8 + lr) * B_STRIDE
                              + (uint32_t)(wn + j * 16 + (li >> 1) * 8) * 2;
                uint32_t t4[4];
                ldsm_x4_t(t4, addr);
#pragma unroll
                for (int mt = 0; mt < 2; mt++) {
                    mma_f16(acc[mt][2 * j],     af[mt], t4[0], t4[1]);
                    mma_f16(acc[mt][2 * j + 1], af[mt], t4[2], t4[3]);
                }
            }
        }
        __syncthreads();
    }

    int g = lane >> 2, tg = lane & 3;
#pragma unroll
    for (int mt = 0; mt < 2; mt++) {
        int m = mbase + wm + mt * 16 + g;
        float bv0 = bias[m], bv1 = bias[m + 8];
        float* po0 = out + ((size_t)bz * M + m) * NN + n0 + wn + tg * 2;
        float* po1 = po0 + 8 * (size_t)NN;
#pragma unroll
        for (int nt = 0; nt < 8; nt++) {
            *(float2*)(po0 + nt * 8) = make_float2(acc[mt][nt][0] + bv0, acc[mt][nt][1] + bv0);
            *(float2*)(po1 + nt * 8) = make_float2(acc[mt][nt][2] + bv1, acc[mt][nt][3] + bv1);
        }
    }
}

// ---------------- single-pass focusing transform (q and k), 32 pixels/block ----------------
#define FOC_PIX 32
#define FOC_STR 33
#define FOC_SMEM (256 * FOC_STR * 4 + 256 * 4 + 256 * 4 + 256 * 4 + FOC_PIX * 4)
__global__ __launch_bounds__(256)
void focus_kernel() {
    extern __shared__ char fsm[];
    float* tile = (float*)fsm;                            // 256 x 33
    float* sinv = (float*)(fsm + 256 * FOC_STR * 4);      // 256
    float* sp2  = sinv + 256;                             // 8 x 32
    float* sp6  = sp2 + 256;                              // 8 x 32
    float* sf   = sp6 + 256;                              // 32
    int tid = threadIdx.x;
    int part = blockIdx.y, b = blockIdx.z;
    int n0 = blockIdx.x * FOC_PIX;
    sinv[tid] = g_invscale[tid];
    float* base = g_qkv + ((size_t)b * M_QKV + part * CC) * NN + n0;
    int j = tid & 31, ci = tid >> 5;
    __syncthreads();
#pragma unroll 8
    for (int i = 0; i < 32; i++) {
        int c = i * 8 + ci;
        float v = base[(size_t)c * NN + j];
        v = fmaxf(v, 0.f) + 1e-6f;
        tile[c * FOC_STR + j] = v * sinv[c];
    }
    __syncthreads();
    float s2 = 0.f, s6 = 0.f;
#pragma unroll 8
    for (int c = ci * 32; c < ci * 32 + 32; c++) {
        float v = tile[c * FOC_STR + j];
        float v2 = v * v, v3 = v2 * v;
        s2 += v2; s6 += v3 * v3;
        tile[c * FOC_STR + j] = v3;
    }
    sp2[ci * 32 + j] = s2;
    sp6[ci * 32 + j] = s6;
    __syncthreads();
    if (tid < 32) {
        float t2 = 0.f, t6 = 0.f;
#pragma unroll
        for (int gq = 0; gq < 8; gq++) { t2 += sp2[gq * 32 + tid]; t6 += sp6[gq * 32 + tid]; }
        sf[tid] = sqrtf(t2 / t6);
    }
    __syncthreads();
    float f = sf[j];
#pragma unroll 8
    for (int i = 0; i < 32; i++) {
        int c = i * 8 + ci;
        base[(size_t)c * NN + j] = tile[c * FOC_STR + j] * f;
    }
}

// ---------------- per-head kv_state partials: j-major smem, float4 inner loads ----------------
#define CHUNK 128
#define JSTR 36
__global__ __launch_bounds__(256)
void kvstate_kernel() {
    int bh = blockIdx.x, seg = blockIdx.y;
    int b = bh >> 3, h = bh & 7;
    const float* kbase = g_qkv + ((size_t)b * M_QKV + CC + h * HD) * NN;
    const float* vbase = g_qkv + ((size_t)b * M_QKV + 2 * CC + h * HD) * NN;
    __shared__ __align__(16) float sk[CHUNK * JSTR];
    __shared__ __align__(16) float sv[CHUNK * JSTR];
    int tid = threadIdx.x;
    int c = tid >> 3, d4 = (tid & 7) * 4;
    int lc = tid >> 3, lj4 = (tid & 7) * 4;
    float acc[4] = {0, 0, 0, 0};
    float ks = 0.f;
    int j_begin = seg * (NN / SEGS);

    for (int j0 = j_begin; j0 < j_begin + NN / SEGS; j0 += CHUNK) {
#pragma unroll
        for (int jj = 0; jj < CHUNK; jj += 32) {
            float4 k4 = *(const float4*)(kbase + (size_t)lc * NN + j0 + jj + lj4);
            float4 v4 = *(const float4*)(vbase + (size_t)lc * NN + j0 + jj + lj4);
            sk[(jj + lj4 + 0) * JSTR + lc] = k4.x;
            sk[(jj + lj4 + 1) * JSTR + lc] = k4.y;
            sk[(jj + lj4 + 2) * JSTR + lc] = k4.z;
            sk[(jj + lj4 + 3) * JSTR + lc] = k4.w;
            sv[(jj + lj4 + 0) * JSTR + lc] = v4.x;
            sv[(jj + lj4 + 1) * JSTR + lc] = v4.y;
            sv[(jj + lj4 + 2) * JSTR + lc] = v4.z;
            sv[(jj + lj4 + 3) * JSTR + lc] = v4.w;
        }
        __syncthreads();
#pragma unroll 4
        for (int j = 0; j < CHUNK; j++) {
            float kc = sk[j * JSTR + c];
            ks += kc;
            float4 v = *(const float4*)(sv + j * JSTR + d4);
            acc[0] += kc * v.x;
            acc[1] += kc * v.y;
            acc[2] += kc * v.z;
            acc[3] += kc * v.w;
        }
        __syncthreads();
    }
    float* kvs = g_kvp + ((size_t)seg * BB * NH + bh) * HD * HD;
#pragma unroll
    for (int i = 0; i < 4; i++) kvs[c * HD + d4 + i] = acc[i];
    if ((tid & 7) == 0) g_ksp[((size_t)seg * BB * NH + bh) * HD + c] = ks;
}

// ---------------- fused depthwise conv + attention output -> fp16 mid ----------------
__global__ __launch_bounds__(256)
void conv_attn_kernel(const float* __restrict__ dwc_w, const float* __restrict__ dwc_b) {
    __shared__ float skvs[HD * HD];
    __shared__ float sks[HD];
    __shared__ float tile4[4][20][21];
    __shared__ float wloc4[4][25];
    int bh = blockIdx.y;
    int b = bh >> 3, h = bh & 7;
    int ty0 = (blockIdx.x >> 2) * 16;
    int tx0 = (blockIdx.x & 3) * 16;
    int tid = threadIdx.x, lx = tid & 15, ly = tid >> 4;
    int gy = ty0 + ly, gx = tx0 + lx;
    int n = gy * WW + gx;

    for (int i = tid; i < HD * HD; i += 256) {
        float s = 0.f;
#pragma unroll
        for (int seg = 0; seg < SEGS; seg++)
            s += g_kvp[((size_t)seg * BB * NH + bh) * HD * HD + i];
        skvs[i] = s;
    }
    if (tid < HD) {
        float s = 0.f;
#pragma unroll
        for (int seg = 0; seg < SEGS; seg++)
            s += g_ksp[((size_t)seg * BB * NH + bh) * HD + tid];
        sks[tid] = s;
    }

    float acc[HD];
    const float* vball = g_qkv + ((size_t)b * M_QKV + 2 * CC + h * HD) * NN;
    for (int d0 = 0; d0 < HD; d0 += 4) {
        __syncthreads();
        if (tid < 100) wloc4[tid / 25][tid % 25] = dwc_w[(d0 + tid / 25) * 25 + tid % 25];
        for (int i = tid; i < 1600; i += 256) {
            int ch = i / 400, r = i % 400;
            int ry = r / 20, rx = r % 20;
            int sy = ty0 - 2 + ry, sx = tx0 - 2 + rx;
            float v = 0.f;
            if (sy >= 0 && sy < HH && sx >= 0 && sx < WW)
                v = vball[(size_t)(d0 + ch) * NN + sy * WW + sx];
            tile4[ch][ry][rx] = v;
        }
        __syncthreads();
#pragma unroll
        for (int ch = 0; ch < 4; ch++) {
            float a = dwc_b[d0 + ch];
#pragma unroll
            for (int ky = 0; ky < 5; ky++)
#pragma unroll
                for (int kx = 0; kx < 5; kx++)
                    a += tile4[ch][ly + ky][lx + kx] * wloc4[ch][ky * 5 + kx];
            acc[d0 + ch] = a;
        }
    }
    __syncthreads();

    const float* qbase = g_qkv + ((size_t)b * M_QKV + h * HD) * NN + n;
    float a2[HD];
#pragma unroll
    for (int d = 0; d < HD; d++) a2[d] = 0.f;
    float zacc = 0.f;
#pragma unroll
    for (int c = 0; c < HD; c++) {
        float qv = qbase[(size_t)c * NN];
        zacc += qv * sks[c];
#pragma unroll
        for (int d = 0; d < HD; d++) a2[d] += qv * skvs[c * HD + d];
    }
    float z = 1.0f / (zacc + 1e-6f);
    __half* mh = (__half*)g_mh4;
#pragma unroll
    for (int d = 0; d < HD; d++) {
        size_t off = ((size_t)b * CC + h * HD + d) * NN + n;
        mh[off] = __float2half(acc[d] + a2[d] * z);
    }
}

// ---------------- launch ----------------
extern "C" void kernel_launch(void* const* d_in, const int* in_sizes, int n_in,
                              void* d_out, int out_size) {
    const float* x           = (const float*)d_in[0];
    const float* Wq          = (const float*)d_in[1];
    const float* bq          = (const float*)d_in[2];
    const float* Wkv         = (const float*)d_in[3];
    const float* bkv         = (const float*)d_in[4];
    const float* Wproj       = (const float*)d_in[5];
    const float* bproj       = (const float*)d_in[6];
    const float* dwc_w       = (const float*)d_in[7];
    const float* dwc_b       = (const float*)d_in[8];
    const float* scale_param = (const float*)d_in[9];
    float* out = (float*)d_out;

    float *p_qkv, *p_bcat;
    uint4 *p_wh, *p_pwh, *p_xh, *p_mh;
    cudaGetSymbolAddress((void**)&p_qkv,  g_qkv);
    cudaGetSymbolAddress((void**)&p_bcat, g_bcat);
    cudaGetSymbolAddress((void**)&p_wh,   g_wh4);
    cudaGetSymbolAddress((void**)&p_pwh,  g_pwh4);
    cudaGetSymbolAddress((void**)&p_xh,   g_xh4);
    cudaGetSymbolAddress((void**)&p_mh,   g_mh4);

    cudaFuncSetAttribute(gemm_mma_kernel, cudaFuncAttributeMaxDynamicSharedMemorySize, SM_GEMM);
    cudaFuncSetAttribute(focus_kernel, cudaFuncAttributeMaxDynamicSharedMemorySize, FOC_SMEM);

    prep_kernel<<<M_QKV, CC>>>(Wq, bq, Wkv, bkv, Wproj, scale_param);

    int n4 = BB * CC * NN / 4;
    split_kernel<<<(n4 + 255) / 256, 256>>>((const float4*)x, (__half*)p_xh, n4);

    // QKV projection: 768x256 @ 256x4096 per batch
    gemm_mma_kernel<<<dim3(NN / 128, M_QKV / 128, BB), 256, SM_GEMM>>>(
        (const __half*)p_wh, (const __half*)p_xh, p_bcat, p_qkv, M_QKV);

    focus_kernel<<<dim3(NN / FOC_PIX, 2, BB), 256, FOC_SMEM>>>();

    kvstate_kernel<<<dim3(BB * NH, SEGS), 256>>>();

    conv_attn_kernel<<<dim3(16, BB * NH), 256>>>(dwc_w, dwc_b);

    // Output projection: 256x256 @ 256x4096 per batch -> d_out
    gemm_mma_kernel<<<dim3(NN / 128, CC / 128, BB), 256, SM_GEMM>>>(
        (const __half*)p_pwh, (const __half*)p_mh, bproj, out, CC);
}